// round 3
// baseline (speedup 1.0000x reference)
#include <cuda_runtime.h>
#include <cuda_bf16.h>
#include <cstdint>

// ---------------------------------------------------------------------------
// EdgeConv (mlp_layer=0, aggregate=max), restructured:
//   t      = feat @ theta_w                      [N, 64]
//   base   = t + feat @ phi_w + theta_b + phi_b  [N, 64]   (written to d_out)
//   out[v] = base[v] - min_k t[nbr[v,k]]         (per-feature min)
//
// GEMM on legacy tensor cores (mma.sync bf16, hi/lo split, 3 passes), since
// this toolchain targets sm_100 (no 'a' suffix) -> tcgen05 unavailable.
// ---------------------------------------------------------------------------

#define F_DIM 64
#define N_MAX 120000
#define PADK  72                       // bf16 row stride (64 + 8 pad) = 144 B

__device__ float g_t[(size_t)N_MAX * F_DIM];   // scratch for t

// ============================= PTX helpers =================================
__device__ __forceinline__ uint32_t smem_u32(const void* p) {
    uint32_t a;
    asm("{ .reg .u64 tmp; cvta.to.shared.u64 tmp, %1; cvt.u32.u64 %0, tmp; }"
        : "=r"(a) : "l"(p));
    return a;
}

__device__ __forceinline__ void ldsm_x4(uint32_t* r, uint32_t addr) {
    asm volatile("ldmatrix.sync.aligned.m8n8.x4.shared.b16 {%0,%1,%2,%3}, [%4];"
                 : "=r"(r[0]), "=r"(r[1]), "=r"(r[2]), "=r"(r[3]) : "r"(addr));
}

__device__ __forceinline__ void mma16816(float* c, const uint32_t* a,
                                         const uint32_t* b) {
    asm volatile(
        "mma.sync.aligned.m16n8k16.row.col.f32.bf16.bf16.f32 "
        "{%0,%1,%2,%3}, {%4,%5,%6,%7}, {%8,%9}, {%0,%1,%2,%3};"
        : "+f"(c[0]), "+f"(c[1]), "+f"(c[2]), "+f"(c[3])
        : "r"(a[0]), "r"(a[1]), "r"(a[2]), "r"(a[3]), "r"(b[0]), "r"(b[1]));
}

__device__ __forceinline__ uint32_t pack_hi(float x, float y,
                                            uint32_t& lo_out) {
    __nv_bfloat16 hx = __float2bfloat16(x);
    __nv_bfloat16 hy = __float2bfloat16(y);
    __nv_bfloat16 lx = __float2bfloat16(x - __bfloat162float(hx));
    __nv_bfloat16 ly = __float2bfloat16(y - __bfloat162float(hy));
    lo_out = (uint32_t)__bfloat16_as_ushort(lx) |
             ((uint32_t)__bfloat16_as_ushort(ly) << 16);
    return (uint32_t)__bfloat16_as_ushort(hx) |
           ((uint32_t)__bfloat16_as_ushort(hy) << 16);
}

// SMEM layout (dynamic): 4 tiles of 128 rows x PADK bf16
#define SM_AHI 0
#define SM_ALO (128 * PADK * 2)
#define SM_BHI (2 * 128 * PADK * 2)
#define SM_BLO (3 * 128 * PADK * 2)
#define SM_BYTES (4 * 128 * PADK * 2)   // 73728

// ============================ GEMM kernel ==================================
__global__ __launch_bounds__(256)
void gemm_mma_kernel(const float* __restrict__ feat,
                     const float* __restrict__ theta_w,
                     const float* __restrict__ theta_b,
                     const float* __restrict__ phi_w,
                     const float* __restrict__ phi_b,
                     float* __restrict__ out,
                     int n)
{
    extern __shared__ char sm[];
    const uint32_t sbase = smem_u32(sm);
    const int tid = threadIdx.x;
    const int rb  = blockIdx.x * 128;

    // ---- stage A: feat[rb..rb+127][0..63] -> bf16 hi/lo (coalesced) -------
#pragma unroll
    for (int it = 0; it < 16; it++) {
        int idx = tid + it * 256;        // 0..4095
        int kp  = idx & 31;              // k pair
        int row = idx >> 5;
        float2 f = make_float2(0.f, 0.f);
        int gr = rb + row;
        if (gr < n) f = *(const float2*)&feat[(size_t)gr * F_DIM + 2 * kp];
        uint32_t lw, hw = pack_hi(f.x, f.y, lw);
        *(uint32_t*)(sm + SM_AHI + row * 144 + kp * 4) = hw;
        *(uint32_t*)(sm + SM_ALO + row * 144 + kp * 4) = lw;
    }

    // ---- stage B (col-major k x n == Bt[n][k]): n<64 theta, n>=64 phi ------
#pragma unroll
    for (int it = 0; it < 16; it++) {
        int idx  = tid + it * 256;       // 0..4095
        int kp   = idx & 31;
        int nrow = idx >> 5;             // 0..127
        const float* w = (nrow < 64) ? theta_w : phi_w;
        int nc = nrow & 63;
        float w0 = w[(2 * kp) * F_DIM + nc];
        float w1 = w[(2 * kp + 1) * F_DIM + nc];
        uint32_t lw, hw = pack_hi(w0, w1, lw);
        *(uint32_t*)(sm + SM_BHI + nrow * 144 + kp * 4) = hw;
        *(uint32_t*)(sm + SM_BLO + nrow * 144 + kp * 4) = lw;
    }
    __syncthreads();

    const int wid  = tid >> 5;
    const int lane = tid & 31;
    const int wm   = (wid & 3) * 32;     // warp M offset
    const int wn   = (wid >> 2) * 32;    // warp N offset (theta side)
    const int li   = lane & 7;
    const int lg   = lane >> 3;

    // accumulators: c[q][mt][4]; q 0..3 = theta tiles (cols wn+8q),
    //                            q 4..7 = phi tiles  (cols 64+wn+8(q-4))
    float c[8][2][4];
#pragma unroll
    for (int q = 0; q < 8; q++)
#pragma unroll
        for (int mt = 0; mt < 2; mt++)
#pragma unroll
            for (int j = 0; j < 4; j++) c[q][mt][j] = 0.f;

#pragma unroll
    for (int p = 0; p < 3; p++) {
        const uint32_t aoff = (p == 1) ? SM_ALO : SM_AHI;
        const uint32_t boff = (p == 2) ? SM_BLO : SM_BHI;
#pragma unroll
        for (int ks = 0; ks < 4; ks++) {
            const int k0 = ks * 16;
            uint32_t a[2][4];
#pragma unroll
            for (int mt = 0; mt < 2; mt++) {
                int row = wm + mt * 16 + li + (lg & 1) * 8;
                int col = k0 + (lg >> 1) * 8;
                ldsm_x4(a[mt], sbase + aoff + row * 144 + col * 2);
            }
            uint32_t b[8][2];
#pragma unroll
            for (int jp = 0; jp < 4; jp++) {
                // jp: 0 -> theta n=wn, 1 -> theta n=wn+16,
                //     2 -> phi 64+wn,  3 -> phi 64+wn+16   (each covers 2 tiles)
                int nb  = wn + (jp & 1) * 16 + (jp >> 1) * 64;
                int row = nb + li + (lg >> 1) * 8;
                int col = k0 + (lg & 1) * 8;
                uint32_t r[4];
                ldsm_x4(r, sbase + boff + row * 144 + col * 2);
                int q0 = (jp & 1) * 2 + (jp >> 1) * 4;   // tile index base
                b[q0][0]     = r[0]; b[q0][1]     = r[1];
                b[q0 + 1][0] = r[2]; b[q0 + 1][1] = r[3];
            }
#pragma unroll
            for (int q = 0; q < 8; q++)
#pragma unroll
                for (int mt = 0; mt < 2; mt++)
                    mma16816(c[q][mt], a[mt], b[q]);
        }
    }

    // ---- epilogue: direct register combine + store -------------------------
    // fragment rows: r0 = base + lane/4 (c0,c1), r1 = r0+8 (c2,c3)
    // fragment cols: 2*(lane&3), +1
#pragma unroll
    for (int mt = 0; mt < 2; mt++) {
        int r0 = rb + wm + mt * 16 + (lane >> 2);
#pragma unroll
        for (int j = 0; j < 4; j++) {
            int col = wn + j * 8 + 2 * (lane & 3);
            float b0 = theta_b[col]     + phi_b[col];
            float b1 = theta_b[col + 1] + phi_b[col + 1];
            // row r0
            if (r0 < n) {
                size_t o = (size_t)r0 * F_DIM + col;
                float t0 = c[j][mt][0], t1 = c[j][mt][1];
                *(float2*)&g_t[o] = make_float2(t0, t1);
                *(float2*)&out[o] = make_float2(t0 + c[4 + j][mt][0] + b0,
                                                t1 + c[4 + j][mt][1] + b1);
            }
            int r1 = r0 + 8;
            if (r1 < n) {
                size_t o = (size_t)r1 * F_DIM + col;
                float t2 = c[j][mt][2], t3 = c[j][mt][3];
                *(float2*)&g_t[o] = make_float2(t2, t3);
                *(float2*)&out[o] = make_float2(t2 + c[4 + j][mt][2] + b0,
                                                t3 + c[4 + j][mt][3] + b1);
            }
        }
    }
}

// ============================ gather-min ===================================
// One warp per node; lane owns 2 features (float2). Index dtype (int64 vs
// int32) detected per-warp via ballot on the first 32 words (high words of
// int64 indices are all zero; random int32 indices make that impossible).
__global__ __launch_bounds__(256)
void gather_min_kernel(const void* __restrict__ nbr_raw,
                       float* __restrict__ out,
                       int n, int K)
{
    const int lane = threadIdx.x & 31;

    unsigned int probe = ((const unsigned int*)nbr_raw)[lane];
    bool oddzero = ((lane & 1) == 0) || (probe == 0u);
    const bool is64 = (__ballot_sync(0xFFFFFFFFu, oddzero) == 0xFFFFFFFFu);

    int w = (int)((blockIdx.x * (long long)blockDim.x + threadIdx.x) >> 5);
    if (w >= n) return;

    const float2* t2 = (const float2*)g_t;
    float2 m = make_float2(3.402823466e+38f, 3.402823466e+38f);

    if (K == 16) {
        long long u[16];
        if (is64) {
            const long long* nb = (const long long*)nbr_raw + (long long)w * 16;
#pragma unroll
            for (int j = 0; j < 16; j++) u[j] = nb[j];
        } else {
            const int* nb = (const int*)nbr_raw + (long long)w * 16;
#pragma unroll
            for (int j = 0; j < 16; j++) u[j] = (long long)nb[j];
        }
#pragma unroll
        for (int j = 0; j < 16; j++) {
            float2 v = __ldg(&t2[u[j] * 32 + lane]);
            m.x = fminf(m.x, v.x);
            m.y = fminf(m.y, v.y);
        }
    } else {
        for (int j = 0; j < K; j++) {
            long long u = is64 ? ((const long long*)nbr_raw)[(long long)w * K + j]
                               : (long long)((const int*)nbr_raw)[(long long)w * K + j];
            float2 v = __ldg(&t2[u * 32 + lane]);
            m.x = fminf(m.x, v.x);
            m.y = fminf(m.y, v.y);
        }
    }

    long long o = (long long)w * 32 + lane;
    float2* out2 = (float2*)out;
    float2 b = out2[o];
    b.x -= m.x;
    b.y -= m.y;
    out2[o] = b;
}

// ============================== launch =====================================
extern "C" void kernel_launch(void* const* d_in, const int* in_sizes, int n_in,
                              void* d_out, int out_size)
{
    const float* feat    = (const float*)d_in[0];
    const void*  nbr     = d_in[1];
    const float* theta_w = (const float*)d_in[2];
    const float* theta_b = (const float*)d_in[3];
    const float* phi_w   = (const float*)d_in[4];
    const float* phi_b   = (const float*)d_in[5];
    float* out = (float*)d_out;

    const int n = in_sizes[0] / F_DIM;     // number of nodes
    const int K = in_sizes[1] / n;         // neighbors per node (=16)

    static int smem_set = 0;
    if (!smem_set) {
        cudaFuncSetAttribute(gemm_mma_kernel,
                             cudaFuncAttributeMaxDynamicSharedMemorySize,
                             SM_BYTES);
        smem_set = 1;
    }

    int g1 = (n + 127) / 128;
    gemm_mma_kernel<<<g1, 256, SM_BYTES>>>(feat, theta_w, theta_b, phi_w,
                                           phi_b, out, n);

    long long total_threads = (long long)n * 32;
    int g2 = (int)((total_threads + 255) / 256);
    gather_min_kernel<<<g2, 256>>>(nbr, out, n, K);
}

// round 4
// speedup vs baseline: 1.3571x; 1.3571x over previous
#include <cuda_runtime.h>
#include <cuda_bf16.h>
#include <cuda_fp16.h>
#include <cstdint>

// ---------------------------------------------------------------------------
// EdgeConv (mlp_layer=0, aggregate=max), restructured:
//   t      = feat @ theta_w                      [N, 64]
//   base   = t + feat @ phi_w + theta_b + phi_b  [N, 64]   (written to d_out)
//   out[v] = base[v] - min_k t[nbr[v,k]]         (per-feature min)
//
// GEMM: fp32 FFMA SGEMM (measured at ~100% of FFMA-pipe roofline; tcgen05 is
// unavailable on this sm_100 toolchain target and legacy HMMA is slower).
// Gather: t stored as fp16 -> halves the L2-bound gather stream.
// ---------------------------------------------------------------------------

#define F_DIM 64
#define N_MAX 120000

__device__ __half g_t16[(size_t)N_MAX * F_DIM];   // fp16 t for the gather

// ---------------------------------------------------------------------------
// Kernel 1: fused SGEMM  C = feat @ [theta_w | phi_w]   (M=N nodes, N=128, K=64)
// BM=128 rows/block, 256 threads, 8x(4+4) register tile per thread.
// Each thread owns output features tx*4..tx*4+3 for BOTH theta and phi halves,
// so base = accT + accP combines locally; t written as fp16.
// ---------------------------------------------------------------------------
#define BM 128
#define BK 32
#define TM 8
#define TN 4

__global__ __launch_bounds__(256)
void fused_gemm_kernel(const float* __restrict__ feat,
                       const float* __restrict__ theta_w,
                       const float* __restrict__ theta_b,
                       const float* __restrict__ phi_w,
                       const float* __restrict__ phi_b,
                       float* __restrict__ out,
                       int n)
{
    __shared__ float sA[BK][BM + 1];   // [k][row]  (transposed feat tile)
    __shared__ float sB[BK][128];      // [k][c]    c<64: theta_w, c>=64: phi_w

    const int tid = threadIdx.x;
    const int tx  = tid & 15;    // 0..15 -> feature group (4 feats)
    const int ty  = tid >> 4;    // 0..15 -> row group (8 rows)
    const int rb  = blockIdx.x * BM;

    float accT[TM][TN], accP[TM][TN];
#pragma unroll
    for (int i = 0; i < TM; i++)
#pragma unroll
        for (int j = 0; j < TN; j++) { accT[i][j] = 0.f; accP[i][j] = 0.f; }

    for (int kk = 0; kk < F_DIM; kk += BK) {
        // --- load A tile (transposed): sA[k][row] = feat[row][kk+k] ---
        {
            const int c  = tid & 31;   // k within chunk
            const int r0 = tid >> 5;   // 0..7
#pragma unroll
            for (int p = 0; p < 16; p++) {
                int r   = r0 + p * 8;
                int row = rb + r;
                sA[c][r] = (row < n) ? feat[(size_t)row * F_DIM + kk + c] : 0.f;
            }
        }
        // --- load B tile: sB[k][c] ---
        {
#pragma unroll
            for (int p = 0; p < 16; p++) {
                int idx = tid + p * 256;          // 0..4095
                int k   = idx >> 7;               // 0..31
                int c   = idx & 127;              // 0..127
                float v = (c < 64) ? theta_w[(kk + k) * F_DIM + c]
                                   : phi_w[(kk + k) * F_DIM + (c - 64)];
                sB[k][c] = v;
            }
        }
        __syncthreads();

#pragma unroll
        for (int k = 0; k < BK; k++) {
            float a[TM];
#pragma unroll
            for (int i = 0; i < TM; i++) a[i] = sA[k][ty * TM + i];
            float4 bT = *(const float4*)&sB[k][tx * 4];
            float4 bP = *(const float4*)&sB[k][64 + tx * 4];
#pragma unroll
            for (int i = 0; i < TM; i++) {
                accT[i][0] += a[i] * bT.x;  accT[i][1] += a[i] * bT.y;
                accT[i][2] += a[i] * bT.z;  accT[i][3] += a[i] * bT.w;
                accP[i][0] += a[i] * bP.x;  accP[i][1] += a[i] * bP.y;
                accP[i][2] += a[i] * bP.z;  accP[i][3] += a[i] * bP.w;
            }
        }
        __syncthreads();
    }

    // --- epilogue: write t (fp16) and base (fp32) ---
    float bias[TN];
#pragma unroll
    for (int j = 0; j < TN; j++) bias[j] = theta_b[tx * 4 + j] + phi_b[tx * 4 + j];

#pragma unroll
    for (int i = 0; i < TM; i++) {
        int row = rb + ty * TM + i;
        if (row < n) {
            size_t off = (size_t)row * F_DIM + tx * 4;
            __half2 h0 = __floats2half2_rn(accT[i][0], accT[i][1]);
            __half2 h1 = __floats2half2_rn(accT[i][2], accT[i][3]);
            *(__half2*)&g_t16[off]     = h0;
            *(__half2*)&g_t16[off + 2] = h1;
            float4 bv = make_float4(accT[i][0] + accP[i][0] + bias[0],
                                    accT[i][1] + accP[i][1] + bias[1],
                                    accT[i][2] + accP[i][2] + bias[2],
                                    accT[i][3] + accP[i][3] + bias[3]);
            *(float4*)&out[off] = bv;
        }
    }
}

// ---------------------------------------------------------------------------
// Kernel 2: gather-min over fp16 t. One warp per node; lane owns 2 features
// (one half2, 4 B) -> warp reads 128 B per neighbor row (1 cache line).
// All offset math in 32-bit (u*32 + lane < 2^22). Index dtype (int64 vs int32)
// detected per-warp via ballot on the first 32 words.
// ---------------------------------------------------------------------------
__global__ __launch_bounds__(256)
void gather_min_kernel(const void* __restrict__ nbr_raw,
                       float* __restrict__ out,
                       int n, int K)
{
    const int lane = threadIdx.x & 31;

    unsigned int probe = ((const unsigned int*)nbr_raw)[lane];
    bool oddzero = ((lane & 1) == 0) || (probe == 0u);
    const bool is64 = (__ballot_sync(0xFFFFFFFFu, oddzero) == 0xFFFFFFFFu);

    int w = (int)((blockIdx.x * (long long)blockDim.x + threadIdx.x) >> 5);
    if (w >= n) return;

    const __half2* t2 = (const __half2*)g_t16;
    __half2 m = __float2half2_rn(65504.f);

    if (K == 16) {
        int u[16];
        if (is64) {
            const longlong2* nb = (const longlong2*)((const long long*)nbr_raw
                                                     + (size_t)w * 16);
#pragma unroll
            for (int j = 0; j < 8; j++) {
                longlong2 p = __ldg(&nb[j]);
                u[2 * j]     = (int)p.x;
                u[2 * j + 1] = (int)p.y;
            }
        } else {
            const int4* nb = (const int4*)((const int*)nbr_raw + (size_t)w * 16);
#pragma unroll
            for (int j = 0; j < 4; j++) {
                int4 p = __ldg(&nb[j]);
                u[4 * j]     = p.x;
                u[4 * j + 1] = p.y;
                u[4 * j + 2] = p.z;
                u[4 * j + 3] = p.w;
            }
        }
#pragma unroll
        for (int j = 0; j < 16; j++) {
            __half2 v = __ldg(&t2[u[j] * 32 + lane]);
            m = __hmin2(m, v);
        }
    } else {
        for (int j = 0; j < K; j++) {
            int u = is64 ? (int)((const long long*)nbr_raw)[(size_t)w * K + j]
                         : ((const int*)nbr_raw)[(size_t)w * K + j];
            __half2 v = __ldg(&t2[u * 32 + lane]);
            m = __hmin2(m, v);
        }
    }

    float2 mf = __half22float2(m);
    float2* out2 = (float2*)out;
    size_t o = (size_t)w * 32 + lane;
    float2 b = out2[o];
    b.x -= mf.x;
    b.y -= mf.y;
    out2[o] = b;
}

// ============================== launch =====================================
extern "C" void kernel_launch(void* const* d_in, const int* in_sizes, int n_in,
                              void* d_out, int out_size)
{
    const float* feat    = (const float*)d_in[0];
    const void*  nbr     = d_in[1];
    const float* theta_w = (const float*)d_in[2];
    const float* theta_b = (const float*)d_in[3];
    const float* phi_w   = (const float*)d_in[4];
    const float* phi_b   = (const float*)d_in[5];
    float* out = (float*)d_out;

    const int n = in_sizes[0] / F_DIM;     // number of nodes
    const int K = in_sizes[1] / n;         // neighbors per node (=16)

    int g1 = (n + BM - 1) / BM;
    fused_gemm_kernel<<<g1, 256>>>(feat, theta_w, theta_b, phi_w, phi_b, out, n);

    long long total_threads = (long long)n * 32;
    int g2 = (int)((total_threads + 255) / 256);
    gather_min_kernel<<<g2, 256>>>(nbr, out, n, K);
}